// round 1
// baseline (speedup 1.0000x reference)
#include <cuda_runtime.h>
#include <cuda_bf16.h>
#include <math.h>

#define BB   2
#define TT   1024
#define SS   2048
#define FF   1024
#define NN_  16
#define HH   64
#define MM   2049
#define NHD  1024

// ---- scratch (device globals; no allocations allowed) ----
static __device__ __nv_bfloat16 g_qu[BB*NN_*TT*HH];          // bf16(q + u_bias), [b][n][t][h]
static __device__ float         g_qv[BB*NN_*TT*HH];          // fp32 q + v_bias,  [b][n][t][h]
static __device__ __nv_bfloat16 g_kb[BB*NN_*SS*HH];          // bf16 k, [b][n][s][h]
static __device__ __nv_bfloat16 g_vb[BB*NN_*SS*HH];          // bf16 v, [b][n][s][h]
static __device__ float         g_r [NN_*MM*HH];             // fp32 r, [n][m][h]
static __device__ float         g_lg[(size_t)BB*NN_*TT*SS];  // bias -> logits -> exp(l-m), 256MB
static __device__ float         g_sum[BB*NN_*TT];            // softmax denominators
static __device__ __nv_bfloat16 g_ob[BB*TT*NHD];             // bf16 attention output, [b*t][n*h]

// =====================================================================
// Projection: q = x @ Wq; store bf16(q+u) and fp32(q+v) in BNTH layout
// =====================================================================
__global__ void rk_proj_q(const float* __restrict__ A, const float* __restrict__ W,
                          const float* __restrict__ ub, const float* __restrict__ vb)
{
    __shared__ float As[16][64];
    __shared__ float Bs[16][64];
    const int tid = threadIdx.x;
    const int ty = tid >> 4, tx = tid & 15;
    const int row0 = blockIdx.x * 64, col0 = blockIdx.y * 64;
    float acc[4][4] = {};
    for (int kk = 0; kk < FF; kk += 16) {
        #pragma unroll
        for (int i = tid; i < 1024; i += 256) {
            int r = i >> 4, c = i & 15;
            As[c][r] = A[(size_t)(row0 + r) * FF + kk + c];
        }
        #pragma unroll
        for (int i = tid; i < 1024; i += 256) {
            int r = i >> 6, c = i & 63;
            Bs[r][c] = W[(size_t)(kk + r) * NHD + col0 + c];
        }
        __syncthreads();
        #pragma unroll
        for (int kq = 0; kq < 16; kq++) {
            float a[4], b[4];
            #pragma unroll
            for (int i = 0; i < 4; i++) a[i] = As[kq][ty*4 + i];
            #pragma unroll
            for (int j = 0; j < 4; j++) b[j] = Bs[kq][tx*4 + j];
            #pragma unroll
            for (int i = 0; i < 4; i++)
                #pragma unroll
                for (int j = 0; j < 4; j++)
                    acc[i][j] = fmaf(a[i], b[j], acc[i][j]);
        }
        __syncthreads();
    }
    #pragma unroll
    for (int i = 0; i < 4; i++) {
        int r = row0 + ty*4 + i;
        int b_ = r >> 10, t = r & 1023;
        #pragma unroll
        for (int j = 0; j < 4; j++) {
            int c = col0 + tx*4 + j;
            int n = c >> 6, h = c & 63;
            size_t qi = ((size_t)(b_*NN_ + n)*TT + t)*HH + h;
            float v = acc[i][j];
            g_qu[qi] = __float2bfloat16(v + ub[c]);
            g_qv[qi] = v + vb[c];
        }
    }
}

// =====================================================================
// Projection: k / v = memory @ W; store bf16 in BNSH layout (which: 0=k,1=v)
// =====================================================================
__global__ void rk_proj_kv(const float* __restrict__ A, const float* __restrict__ W, int which)
{
    __shared__ float As[16][64];
    __shared__ float Bs[16][64];
    const int tid = threadIdx.x;
    const int ty = tid >> 4, tx = tid & 15;
    const int row0 = blockIdx.x * 64, col0 = blockIdx.y * 64;
    float acc[4][4] = {};
    for (int kk = 0; kk < FF; kk += 16) {
        #pragma unroll
        for (int i = tid; i < 1024; i += 256) {
            int r = i >> 4, c = i & 15;
            As[c][r] = A[(size_t)(row0 + r) * FF + kk + c];
        }
        #pragma unroll
        for (int i = tid; i < 1024; i += 256) {
            int r = i >> 6, c = i & 63;
            Bs[r][c] = W[(size_t)(kk + r) * NHD + col0 + c];
        }
        __syncthreads();
        #pragma unroll
        for (int kq = 0; kq < 16; kq++) {
            float a[4], b[4];
            #pragma unroll
            for (int i = 0; i < 4; i++) a[i] = As[kq][ty*4 + i];
            #pragma unroll
            for (int j = 0; j < 4; j++) b[j] = Bs[kq][tx*4 + j];
            #pragma unroll
            for (int i = 0; i < 4; i++)
                #pragma unroll
                for (int j = 0; j < 4; j++)
                    acc[i][j] = fmaf(a[i], b[j], acc[i][j]);
        }
        __syncthreads();
    }
    #pragma unroll
    for (int i = 0; i < 4; i++) {
        int r = row0 + ty*4 + i;
        int b_ = r >> 11, s = r & 2047;
        #pragma unroll
        for (int j = 0; j < 4; j++) {
            int c = col0 + tx*4 + j;
            int n = c >> 6, h = c & 63;
            size_t oi = ((size_t)(b_*NN_ + n)*SS + s)*HH + h;
            __nv_bfloat16 v = __float2bfloat16(acc[i][j]);
            if (which == 0) g_kb[oi] = v; else g_vb[oi] = v;
        }
    }
}

// =====================================================================
// Projection: r = rel @ Wr (fp32, [n][m][h]); M=2049 needs row guards
// =====================================================================
__global__ void rk_proj_r(const float* __restrict__ A, const float* __restrict__ W)
{
    __shared__ float As[16][64];
    __shared__ float Bs[16][64];
    const int tid = threadIdx.x;
    const int ty = tid >> 4, tx = tid & 15;
    const int row0 = blockIdx.x * 64, col0 = blockIdx.y * 64;
    float acc[4][4] = {};
    for (int kk = 0; kk < FF; kk += 16) {
        #pragma unroll
        for (int i = tid; i < 1024; i += 256) {
            int r = i >> 4, c = i & 15;
            int gr = row0 + r;
            As[c][r] = (gr < MM) ? A[(size_t)gr * FF + kk + c] : 0.f;
        }
        #pragma unroll
        for (int i = tid; i < 1024; i += 256) {
            int r = i >> 6, c = i & 63;
            Bs[r][c] = W[(size_t)(kk + r) * NHD + col0 + c];
        }
        __syncthreads();
        #pragma unroll
        for (int kq = 0; kq < 16; kq++) {
            float a[4], b[4];
            #pragma unroll
            for (int i = 0; i < 4; i++) a[i] = As[kq][ty*4 + i];
            #pragma unroll
            for (int j = 0; j < 4; j++) b[j] = Bs[kq][tx*4 + j];
            #pragma unroll
            for (int i = 0; i < 4; i++)
                #pragma unroll
                for (int j = 0; j < 4; j++)
                    acc[i][j] = fmaf(a[i], b[j], acc[i][j]);
        }
        __syncthreads();
    }
    #pragma unroll
    for (int i = 0; i < 4; i++) {
        int m = row0 + ty*4 + i;
        if (m >= MM) continue;
        #pragma unroll
        for (int j = 0; j < 4; j++) {
            int c = col0 + tx*4 + j;
            int n = c >> 6, h = c & 63;
            g_r[((size_t)n*MM + m)*HH + h] = acc[i][j];
        }
    }
}

// =====================================================================
// bd = q_v @ r^T per (b,n), scaled, scattered through the relative shift:
//   bd[t,m] -> bias[t, m+t-1023]            (if 0 <= s < S)
//   bd[t,m] -> bias[t-1, m+t+1026]          (if t>=1 and s < S)
// d == 1026 diagonal is zeroed by rk_zdiag.
// =====================================================================
__global__ void rk_bd()
{
    __shared__ float As[16][64];
    __shared__ float Bs[16][64];
    const int tid = threadIdx.x;
    const int ty = tid >> 4, tx = tid & 15;
    const int bn = blockIdx.z;
    const int row0 = blockIdx.x * 64, col0 = blockIdx.y * 64;
    const float* A  = g_qv + (size_t)bn * TT * HH;          // [t][h]
    const float* Bt = g_r  + (size_t)(bn & 15) * MM * HH;   // [m][h]
    float acc[4][4] = {};
    for (int kk = 0; kk < HH; kk += 16) {
        #pragma unroll
        for (int i = tid; i < 1024; i += 256) {
            int r = i >> 4, c = i & 15;
            As[c][r] = A[(size_t)(row0 + r) * HH + kk + c];
        }
        #pragma unroll
        for (int i = tid; i < 1024; i += 256) {
            int r = i & 15, c = i >> 4;
            int gm = col0 + c;
            Bs[r][c] = (gm < MM) ? Bt[(size_t)gm * HH + kk + r] : 0.f;
        }
        __syncthreads();
        #pragma unroll
        for (int kq = 0; kq < 16; kq++) {
            float a[4], b[4];
            #pragma unroll
            for (int i = 0; i < 4; i++) a[i] = As[kq][ty*4 + i];
            #pragma unroll
            for (int j = 0; j < 4; j++) b[j] = Bs[kq][tx*4 + j];
            #pragma unroll
            for (int i = 0; i < 4; i++)
                #pragma unroll
                for (int j = 0; j < 4; j++)
                    acc[i][j] = fmaf(a[i], b[j], acc[i][j]);
        }
        __syncthreads();
    }
    size_t base = (size_t)bn * TT * SS;
    #pragma unroll
    for (int i = 0; i < 4; i++) {
        int t = row0 + ty*4 + i;
        #pragma unroll
        for (int j = 0; j < 4; j++) {
            int m = col0 + tx*4 + j;
            if (m < MM) {
                float val = acc[i][j] * 0.125f;
                int s1 = m + t - 1023;
                if (s1 >= 0 && s1 < SS)
                    g_lg[base + (size_t)t*SS + s1] = val;
                if (t >= 1) {
                    int s2 = m + t + 1026;
                    if (s2 < SS)
                        g_lg[base + (size_t)(t-1)*SS + s2] = val;
                }
            }
        }
    }
}

// zero the d == 1026 diagonal (never written by the scatter)
__global__ void rk_zdiag()
{
    int bn = blockIdx.x;
    int t  = threadIdx.x;
    int s  = t + 1026;
    if (s < SS)
        g_lg[(size_t)bn*TT*SS + (size_t)t*SS + s] = 0.f;
}

// =====================================================================
// logits = bf16round(qk_fp32accum) * scale + bias   (in-place in g_lg)
// =====================================================================
__global__ void rk_qk()
{
    __shared__ float As[16][64];
    __shared__ float Bs[16][64];
    const int tid = threadIdx.x;
    const int ty = tid >> 4, tx = tid & 15;
    const int bn = blockIdx.z;
    const int row0 = blockIdx.x * 64, col0 = blockIdx.y * 64;
    const __nv_bfloat16* A  = g_qu + (size_t)bn * TT * HH;  // [t][h]
    const __nv_bfloat16* Bt = g_kb + (size_t)bn * SS * HH;  // [s][h]
    float acc[4][4] = {};
    for (int kk = 0; kk < HH; kk += 16) {
        #pragma unroll
        for (int i = tid; i < 1024; i += 256) {
            int r = i >> 4, c = i & 15;
            As[c][r] = __bfloat162float(A[(size_t)(row0 + r) * HH + kk + c]);
        }
        #pragma unroll
        for (int i = tid; i < 1024; i += 256) {
            int r = i & 15, c = i >> 4;
            Bs[r][c] = __bfloat162float(Bt[(size_t)(col0 + c) * HH + kk + r]);
        }
        __syncthreads();
        #pragma unroll
        for (int kq = 0; kq < 16; kq++) {
            float a[4], b[4];
            #pragma unroll
            for (int i = 0; i < 4; i++) a[i] = As[kq][ty*4 + i];
            #pragma unroll
            for (int j = 0; j < 4; j++) b[j] = Bs[kq][tx*4 + j];
            #pragma unroll
            for (int i = 0; i < 4; i++)
                #pragma unroll
                for (int j = 0; j < 4; j++)
                    acc[i][j] = fmaf(a[i], b[j], acc[i][j]);
        }
        __syncthreads();
    }
    size_t base = (size_t)bn * TT * SS;
    #pragma unroll
    for (int i = 0; i < 4; i++) {
        int t = row0 + ty*4 + i;
        #pragma unroll
        for (int j = 0; j < 4; j++) {
            int s = col0 + tx*4 + j;
            size_t idx = base + (size_t)t*SS + s;
            float qk = __bfloat162float(__float2bfloat16(acc[i][j]));
            g_lg[idx] = qk * 0.125f + g_lg[idx];
        }
    }
}

// =====================================================================
// softmax pass 1: per row, max -> exp(l - max) in place -> sum
// =====================================================================
__global__ void rk_stats()
{
    const int row = blockIdx.x;
    float* p = g_lg + (size_t)row * SS;
    __shared__ float red[256];
    const int tid = threadIdx.x;
    float m = -INFINITY;
    for (int i = tid; i < SS; i += 256) m = fmaxf(m, p[i]);
    red[tid] = m; __syncthreads();
    for (int off = 128; off > 0; off >>= 1) {
        if (tid < off) red[tid] = fmaxf(red[tid], red[tid + off]);
        __syncthreads();
    }
    m = red[0];
    __syncthreads();
    float s = 0.f;
    for (int i = tid; i < SS; i += 256) {
        float u = expf(p[i] - m);
        p[i] = u;
        s += u;
    }
    red[tid] = s; __syncthreads();
    for (int off = 128; off > 0; off >>= 1) {
        if (tid < off) red[tid] += red[tid + off];
        __syncthreads();
    }
    if (tid == 0) g_sum[row] = red[0];
}

// =====================================================================
// out = bf16(u/sum) @ v  (fp32 accum, bf16-rounded result, [b*t][n*h])
// =====================================================================
__global__ void rk_pv()
{
    __shared__ float As[16][64];
    __shared__ float Bs[16][64];
    __shared__ float Ssum[64];
    const int tid = threadIdx.x;
    const int ty = tid >> 4, tx = tid & 15;
    const int bn = blockIdx.z;
    const int b_ = bn >> 4, n = bn & 15;
    const int row0 = blockIdx.x * 64;
    const float* U = g_lg + (size_t)bn * TT * SS;           // [t][s] (= exp(l-m))
    const __nv_bfloat16* V = g_vb + (size_t)bn * SS * HH;   // [s][h]
    if (tid < 64) Ssum[tid] = g_sum[bn*TT + row0 + tid];
    __syncthreads();
    float acc[4][4] = {};
    for (int kk = 0; kk < SS; kk += 16) {
        #pragma unroll
        for (int i = tid; i < 1024; i += 256) {
            int r = i >> 4, c = i & 15;
            float u = U[(size_t)(row0 + r) * SS + kk + c];
            float pr = __fdiv_rn(u, Ssum[r]);
            As[c][r] = __bfloat162float(__float2bfloat16(pr));
        }
        #pragma unroll
        for (int i = tid; i < 1024; i += 256) {
            int r = i >> 6, c = i & 63;
            Bs[r][c] = __bfloat162float(V[(size_t)(kk + r) * HH + c]);
        }
        __syncthreads();
        #pragma unroll
        for (int kq = 0; kq < 16; kq++) {
            float a[4], b[4];
            #pragma unroll
            for (int i = 0; i < 4; i++) a[i] = As[kq][ty*4 + i];
            #pragma unroll
            for (int j = 0; j < 4; j++) b[j] = Bs[kq][tx*4 + j];
            #pragma unroll
            for (int i = 0; i < 4; i++)
                #pragma unroll
                for (int j = 0; j < 4; j++)
                    acc[i][j] = fmaf(a[i], b[j], acc[i][j]);
        }
        __syncthreads();
    }
    #pragma unroll
    for (int i = 0; i < 4; i++) {
        int t = row0 + ty*4 + i;
        #pragma unroll
        for (int j = 0; j < 4; j++) {
            int h = tx*4 + j;
            g_ob[(size_t)(b_*TT + t)*NHD + n*HH + h] = __float2bfloat16(acc[i][j]);
        }
    }
}

// =====================================================================
// final: y = fp32(out_b) @ Wout + b_out
// =====================================================================
__global__ void rk_out(const float* __restrict__ Wout, const float* __restrict__ bo,
                       float* __restrict__ out)
{
    __shared__ float As[16][64];
    __shared__ float Bs[16][64];
    const int tid = threadIdx.x;
    const int ty = tid >> 4, tx = tid & 15;
    const int row0 = blockIdx.x * 64, col0 = blockIdx.y * 64;
    float acc[4][4] = {};
    for (int kk = 0; kk < NHD; kk += 16) {
        #pragma unroll
        for (int i = tid; i < 1024; i += 256) {
            int r = i >> 4, c = i & 15;
            As[c][r] = __bfloat162float(g_ob[(size_t)(row0 + r) * NHD + kk + c]);
        }
        #pragma unroll
        for (int i = tid; i < 1024; i += 256) {
            int r = i >> 6, c = i & 63;
            Bs[r][c] = Wout[(size_t)(kk + r) * FF + col0 + c];
        }
        __syncthreads();
        #pragma unroll
        for (int kq = 0; kq < 16; kq++) {
            float a[4], b[4];
            #pragma unroll
            for (int i = 0; i < 4; i++) a[i] = As[kq][ty*4 + i];
            #pragma unroll
            for (int j = 0; j < 4; j++) b[j] = Bs[kq][tx*4 + j];
            #pragma unroll
            for (int i = 0; i < 4; i++)
                #pragma unroll
                for (int j = 0; j < 4; j++)
                    acc[i][j] = fmaf(a[i], b[j], acc[i][j]);
        }
        __syncthreads();
    }
    #pragma unroll
    for (int i = 0; i < 4; i++) {
        int r = row0 + ty*4 + i;
        #pragma unroll
        for (int j = 0; j < 4; j++) {
            int c = col0 + tx*4 + j;
            out[(size_t)r*FF + c] = acc[i][j] + bo[c];
        }
    }
}

extern "C" void kernel_launch(void* const* d_in, const int* in_sizes, int n_in,
                              void* d_out, int out_size)
{
    (void)in_sizes; (void)n_in; (void)out_size;
    const float* x    = (const float*)d_in[0];
    const float* rel  = (const float*)d_in[1];
    const float* mem  = (const float*)d_in[2];
    const float* Wq   = (const float*)d_in[3];
    const float* Wk   = (const float*)d_in[4];
    const float* Wv   = (const float*)d_in[5];
    const float* Wr   = (const float*)d_in[6];
    const float* ub   = (const float*)d_in[7];
    const float* vb   = (const float*)d_in[8];
    const float* Wout = (const float*)d_in[9];
    const float* bo   = (const float*)d_in[10];
    float* out = (float*)d_out;

    rk_proj_q <<<dim3(BB*TT/64, NHD/64), 256>>>(x, Wq, ub, vb);
    rk_proj_kv<<<dim3(BB*SS/64, NHD/64), 256>>>(mem, Wk, 0);
    rk_proj_kv<<<dim3(BB*SS/64, NHD/64), 256>>>(mem, Wv, 1);
    rk_proj_r <<<dim3((MM+63)/64, NHD/64), 256>>>(rel, Wr);
    rk_bd     <<<dim3(TT/64, (MM+63)/64, BB*NN_), 256>>>();
    rk_zdiag  <<<BB*NN_, TT>>>();
    rk_qk     <<<dim3(TT/64, SS/64, BB*NN_), 256>>>();
    rk_stats  <<<BB*NN_*TT, 256>>>();
    rk_pv     <<<dim3(TT/64, 1, BB*NN_), 256>>>();
    rk_out    <<<dim3(BB*TT/64, FF/64), 256>>>(Wout, bo, out);
}

// round 4
// speedup vs baseline: 1.6761x; 1.6761x over previous
#include <cuda_runtime.h>
#include <cuda_bf16.h>
#include <math.h>

#define BB   2
#define TT   1024
#define SS   2048
#define FF   1024
#define NN_  16
#define HH   64
#define MM   2049
#define NHD  1024

// ---- scratch (device globals; no allocations allowed) ----
static __device__ __nv_bfloat16 g_qu [BB*NN_*TT*HH];          // bf16(q + u_bias), [b][n][t][h]
static __device__ float         g_qv [BB*NN_*TT*HH];          // fp32 q + v_bias,  [b][n][t][h]
static __device__ __nv_bfloat16 g_kb [BB*NN_*SS*HH];          // bf16 k, [b][n][s][h]
static __device__ __nv_bfloat16 g_vbT[BB*NN_*HH*SS];          // bf16 v TRANSPOSED, [b][n][h][s]
static __device__ float         g_r  [NN_*MM*HH];             // fp32 r, [n][m][h]
static __device__ float         g_lg [(size_t)BB*NN_*TT*SS];  // bias -> logits (256MB)
static __device__ float         g_max[BB*NN_*TT];             // softmax row max
static __device__ float         g_sum[BB*NN_*TT];             // softmax denominators
static __device__ __nv_bfloat16 g_ob [BB*TT*NHD];             // bf16 attention output, [b*t][n*h]

__device__ __forceinline__ unsigned pack_bf2(float a, float b) {
    __nv_bfloat162 p = __floats2bfloat162_rn(a, b);
    return *(unsigned*)&p;
}

// ---- warp-level bf16 tensor-core mma (plain sm_103-safe PTX) ----
__device__ __forceinline__ void mma16816(float* d,
                                         unsigned a0, unsigned a1, unsigned a2, unsigned a3,
                                         unsigned b0, unsigned b1) {
    asm volatile(
        "mma.sync.aligned.m16n8k16.row.col.f32.bf16.bf16.f32 "
        "{%0,%1,%2,%3}, {%4,%5,%6,%7}, {%8,%9}, {%0,%1,%2,%3};"
        : "+f"(d[0]), "+f"(d[1]), "+f"(d[2]), "+f"(d[3])
        : "r"(a0), "r"(a1), "r"(a2), "r"(a3), "r"(b0), "r"(b1));
}

// =====================================================================
// FFMA GEMM skeleton: 128x128 tile, 256 threads, 8x8 per thread, K-step 8
// =====================================================================
#define FF_DECL() \
    __shared__ float As[8][132]; \
    __shared__ float Bs[8][132]; \
    const int tid = threadIdx.x; \
    const int ty8 = (tid >> 4) << 3, tx8 = (tid & 15) << 3; \
    float acc[8][8] = {};

#define FF_COMPUTE() \
    { _Pragma("unroll") \
      for (int kq = 0; kq < 8; kq++) { \
        float4 a0 = *(const float4*)&As[kq][ty8]; \
        float4 a1 = *(const float4*)&As[kq][ty8 + 4]; \
        float4 b0 = *(const float4*)&Bs[kq][tx8]; \
        float4 b1 = *(const float4*)&Bs[kq][tx8 + 4]; \
        float av[8] = {a0.x,a0.y,a0.z,a0.w,a1.x,a1.y,a1.z,a1.w}; \
        float bv[8] = {b0.x,b0.y,b0.z,b0.w,b1.x,b1.y,b1.z,b1.w}; \
        _Pragma("unroll") for (int i_ = 0; i_ < 8; i_++) \
        _Pragma("unroll") for (int j_ = 0; j_ < 8; j_++) \
            acc[i_][j_] = fmaf(av[i_], bv[j_], acc[i_][j_]); \
      } }

#define FF_LOAD_A_F32(Aptr, lda) { \
    int r_ = tid >> 1, kc_ = (tid & 1) << 2; \
    float4 v_ = *(const float4*)((Aptr) + (size_t)r_ * (lda) + kc_); \
    As[kc_+0][r_] = v_.x; As[kc_+1][r_] = v_.y; As[kc_+2][r_] = v_.z; As[kc_+3][r_] = v_.w; }

#define FF_LOAD_A_F32_G(Aptr, lda, rowslim) { \
    int r_ = tid >> 1, kc_ = (tid & 1) << 2; \
    float4 v_ = make_float4(0.f,0.f,0.f,0.f); \
    if (r_ < (rowslim)) v_ = *(const float4*)((Aptr) + (size_t)r_ * (lda) + kc_); \
    As[kc_+0][r_] = v_.x; As[kc_+1][r_] = v_.y; As[kc_+2][r_] = v_.z; As[kc_+3][r_] = v_.w; }

#define FF_LOAD_A_BF16(Aptr, lda) { \
    int r_ = tid >> 1, kc_ = (tid & 1) << 2; \
    uint2 w_ = *(const uint2*)((Aptr) + (size_t)r_ * (lda) + kc_); \
    __nv_bfloat162 p0_ = *(__nv_bfloat162*)&w_.x; \
    __nv_bfloat162 p1_ = *(__nv_bfloat162*)&w_.y; \
    As[kc_+0][r_] = __low2float(p0_);  As[kc_+1][r_] = __high2float(p0_); \
    As[kc_+2][r_] = __low2float(p1_);  As[kc_+3][r_] = __high2float(p1_); }

#define FF_LOAD_B_ROW(Bptr, ldb) { \
    int kr_ = tid >> 5, c_ = (tid & 31) << 2; \
    float4 v_ = *(const float4*)((Bptr) + (size_t)kr_ * (ldb) + c_); \
    *(float4*)&Bs[kr_][c_] = v_; }

#define FF_LOAD_B_TRANS_G(Bptr, ldb, rowslim) { \
    int n_ = tid >> 1, kc_ = (tid & 1) << 2; \
    float4 v_ = make_float4(0.f,0.f,0.f,0.f); \
    if (n_ < (rowslim)) v_ = *(const float4*)((Bptr) + (size_t)n_ * (ldb) + kc_); \
    Bs[kc_+0][n_] = v_.x; Bs[kc_+1][n_] = v_.y; Bs[kc_+2][n_] = v_.z; Bs[kc_+3][n_] = v_.w; }

// =====================================================================
// Projection q: x[2048,1024] @ Wq[1024,1024] -> qu bf16(+ub), qv fp32(+vb), BNTH
// =====================================================================
__global__ void __launch_bounds__(256) rk_proj_q(const float* __restrict__ A,
                                                 const float* __restrict__ W,
                                                 const float* __restrict__ ub,
                                                 const float* __restrict__ vb)
{
    FF_DECL();
    const int row0 = blockIdx.x * 128, col0 = blockIdx.y * 128;
    for (int kk = 0; kk < FF; kk += 8) {
        FF_LOAD_A_F32(A + (size_t)row0 * FF + kk, FF);
        FF_LOAD_B_ROW(W + (size_t)kk * NHD + col0, NHD);
        __syncthreads();
        FF_COMPUTE();
        __syncthreads();
    }
    const int cbase = col0 + tx8;
    const int n = cbase >> 6, h0 = cbase & 63;
    float u8[8], v8[8];
    #pragma unroll
    for (int j = 0; j < 8; j++) { u8[j] = ub[cbase + j]; v8[j] = vb[cbase + j]; }
    #pragma unroll
    for (int i = 0; i < 8; i++) {
        int r = row0 + ty8 + i;
        int b_ = r >> 10, t = r & 1023;
        size_t o = ((size_t)(b_*NN_ + n) * TT + t) * HH + h0;
        unsigned w0 = pack_bf2(acc[i][0]+u8[0], acc[i][1]+u8[1]);
        unsigned w1 = pack_bf2(acc[i][2]+u8[2], acc[i][3]+u8[3]);
        unsigned w2 = pack_bf2(acc[i][4]+u8[4], acc[i][5]+u8[5]);
        unsigned w3 = pack_bf2(acc[i][6]+u8[6], acc[i][7]+u8[7]);
        *(uint4*)&g_qu[o] = make_uint4(w0, w1, w2, w3);
        float4 q0 = make_float4(acc[i][0]+v8[0], acc[i][1]+v8[1], acc[i][2]+v8[2], acc[i][3]+v8[3]);
        float4 q1 = make_float4(acc[i][4]+v8[4], acc[i][5]+v8[5], acc[i][6]+v8[6], acc[i][7]+v8[7]);
        *(float4*)&g_qv[o] = q0;
        *(float4*)&g_qv[o + 4] = q1;
    }
}

// =====================================================================
// Projection k: memory[4096,1024] @ Wk -> kb bf16 BNSH
// =====================================================================
__global__ void __launch_bounds__(256) rk_proj_k(const float* __restrict__ A,
                                                 const float* __restrict__ W)
{
    FF_DECL();
    const int row0 = blockIdx.x * 128, col0 = blockIdx.y * 128;
    for (int kk = 0; kk < FF; kk += 8) {
        FF_LOAD_A_F32(A + (size_t)row0 * FF + kk, FF);
        FF_LOAD_B_ROW(W + (size_t)kk * NHD + col0, NHD);
        __syncthreads();
        FF_COMPUTE();
        __syncthreads();
    }
    const int cbase = col0 + tx8;
    const int n = cbase >> 6, h0 = cbase & 63;
    #pragma unroll
    for (int i = 0; i < 8; i++) {
        int r = row0 + ty8 + i;
        int b_ = r >> 11, s = r & 2047;
        size_t o = ((size_t)(b_*NN_ + n) * SS + s) * HH + h0;
        unsigned w0 = pack_bf2(acc[i][0], acc[i][1]);
        unsigned w1 = pack_bf2(acc[i][2], acc[i][3]);
        unsigned w2 = pack_bf2(acc[i][4], acc[i][5]);
        unsigned w3 = pack_bf2(acc[i][6], acc[i][7]);
        *(uint4*)&g_kb[o] = make_uint4(w0, w1, w2, w3);
    }
}

// =====================================================================
// Projection v: memory @ Wv -> vT bf16 [b][n][h][s]
// =====================================================================
__global__ void __launch_bounds__(256) rk_proj_v(const float* __restrict__ A,
                                                 const float* __restrict__ W)
{
    FF_DECL();
    const int row0 = blockIdx.x * 128, col0 = blockIdx.y * 128;
    for (int kk = 0; kk < FF; kk += 8) {
        FF_LOAD_A_F32(A + (size_t)row0 * FF + kk, FF);
        FF_LOAD_B_ROW(W + (size_t)kk * NHD + col0, NHD);
        __syncthreads();
        FF_COMPUTE();
        __syncthreads();
    }
    const int r0 = row0 + ty8;
    const int b_ = r0 >> 11, s0 = r0 & 2047;   // 8 rows stay in one b
    #pragma unroll
    for (int j = 0; j < 8; j++) {
        int c = col0 + tx8 + j;
        int n = c >> 6, h = c & 63;
        unsigned w0 = pack_bf2(acc[0][j], acc[1][j]);
        unsigned w1 = pack_bf2(acc[2][j], acc[3][j]);
        unsigned w2 = pack_bf2(acc[4][j], acc[5][j]);
        unsigned w3 = pack_bf2(acc[6][j], acc[7][j]);
        size_t o = ((size_t)(b_*NN_ + n) * HH + h) * SS + s0;
        *(uint4*)&g_vbT[o] = make_uint4(w0, w1, w2, w3);
    }
}

// =====================================================================
// Projection r: rel[2049,1024] @ Wr -> r fp32 [n][m][h]
// =====================================================================
__global__ void __launch_bounds__(256) rk_proj_r(const float* __restrict__ A,
                                                 const float* __restrict__ W)
{
    FF_DECL();
    const int row0 = blockIdx.x * 128, col0 = blockIdx.y * 128;
    const int rowslim = MM - row0;
    for (int kk = 0; kk < FF; kk += 8) {
        FF_LOAD_A_F32_G(A + (size_t)row0 * FF + kk, FF, rowslim);
        FF_LOAD_B_ROW(W + (size_t)kk * NHD + col0, NHD);
        __syncthreads();
        FF_COMPUTE();
        __syncthreads();
    }
    const int cbase = col0 + tx8;
    const int n = cbase >> 6, h0 = cbase & 63;
    #pragma unroll
    for (int i = 0; i < 8; i++) {
        int m = row0 + ty8 + i;
        if (m >= MM) continue;
        size_t o = ((size_t)n * MM + m) * HH + h0;
        *(float4*)&g_r[o]     = make_float4(acc[i][0], acc[i][1], acc[i][2], acc[i][3]);
        *(float4*)&g_r[o + 4] = make_float4(acc[i][4], acc[i][5], acc[i][6], acc[i][7]);
    }
}

// =====================================================================
// bd = q_v @ r^T per (b,n), scaled, scattered through the relative shift
// =====================================================================
__global__ void __launch_bounds__(256) rk_bd()
{
    FF_DECL();
    const int bn = blockIdx.z;
    const int row0 = blockIdx.x * 128, col0 = blockIdx.y * 128;
    const float* A  = g_qv + (size_t)bn * TT * HH;
    const float* Bt = g_r  + (size_t)(bn & 15) * MM * HH;
    const int rowslim = MM - col0;
    for (int kk = 0; kk < HH; kk += 8) {
        FF_LOAD_A_F32(A + (size_t)row0 * HH + kk, HH);
        FF_LOAD_B_TRANS_G(Bt + (size_t)col0 * HH + kk, HH, rowslim);
        __syncthreads();
        FF_COMPUTE();
        __syncthreads();
    }
    size_t base = (size_t)bn * TT * SS;
    #pragma unroll
    for (int i = 0; i < 8; i++) {
        int t = row0 + ty8 + i;
        #pragma unroll
        for (int j = 0; j < 8; j++) {
            int m = col0 + tx8 + j;
            if (m < MM) {
                float val = acc[i][j] * 0.125f;
                int s1 = m + t - 1023;
                if (s1 >= 0 && s1 < SS)
                    g_lg[base + (size_t)t * SS + s1] = val;
                if (t >= 1) {
                    int s2 = m + t + 1026;
                    if (s2 < SS)
                        g_lg[base + (size_t)(t-1) * SS + s2] = val;
                }
            }
        }
    }
}

// zero the d == 1026 diagonal (never written by the scatter)
__global__ void rk_zdiag()
{
    int bn = blockIdx.x;
    int t  = threadIdx.x;
    int s  = t + 1026;
    if (s < SS)
        g_lg[(size_t)bn*TT*SS + (size_t)t*SS + s] = 0.f;
}

// =====================================================================
// HMMA qk: logits[t,s] = bf16round(qk)*scale + bias  (RMW g_lg)
// tile 128(t) x 128(s), K=64. 8 warps: warp tile 64x32.
// =====================================================================
__global__ void __launch_bounds__(256) rk_qk_mma()
{
    __shared__ __nv_bfloat16 As[128][72];   // qu rows, pad->row stride 144B (16B-mult)
    __shared__ __nv_bfloat16 Bs[128][72];   // kb rows
    const int tid = threadIdx.x, wid = tid >> 5, lane = tid & 31;
    const int g = lane >> 2, tg = lane & 3;
    const int bn = blockIdx.z;
    const int trow0 = blockIdx.x * 128, srow0 = blockIdx.y * 128;
    const int m_base = (wid >> 2) * 64, n_base = (wid & 3) * 32;

    // cooperative load: 2 threads per row, 64B each
    {
        const __nv_bfloat16* Ag = g_qu + ((size_t)bn * TT + trow0) * HH;
        const __nv_bfloat16* Bg = g_kb + ((size_t)bn * SS + srow0) * HH;
        int r = tid >> 1, c0 = (tid & 1) * 32;
        const uint4* as = (const uint4*)(Ag + (size_t)r * HH + c0);
        const uint4* bs = (const uint4*)(Bg + (size_t)r * HH + c0);
        uint4* ad = (uint4*)&As[r][c0];
        uint4* bd = (uint4*)&Bs[r][c0];
        #pragma unroll
        for (int q = 0; q < 4; q++) { ad[q] = as[q]; bd[q] = bs[q]; }
    }
    __syncthreads();

    float acc[4][4][4] = {};
    #pragma unroll
    for (int kk = 0; kk < 64; kk += 16) {
        unsigned af[4][4], bf[4][2];
        #pragma unroll
        for (int i = 0; i < 4; i++) {
            int mr = m_base + i * 16 + g;
            af[i][0] = *(const unsigned*)&As[mr    ][kk + tg*2];
            af[i][1] = *(const unsigned*)&As[mr + 8][kk + tg*2];
            af[i][2] = *(const unsigned*)&As[mr    ][kk + 8 + tg*2];
            af[i][3] = *(const unsigned*)&As[mr + 8][kk + 8 + tg*2];
        }
        #pragma unroll
        for (int j = 0; j < 4; j++) {
            int nr = n_base + j * 8 + g;
            bf[j][0] = *(const unsigned*)&Bs[nr][kk + tg*2];
            bf[j][1] = *(const unsigned*)&Bs[nr][kk + 8 + tg*2];
        }
        #pragma unroll
        for (int i = 0; i < 4; i++)
            #pragma unroll
            for (int j = 0; j < 4; j++)
                mma16816(acc[i][j], af[i][0], af[i][1], af[i][2], af[i][3], bf[j][0], bf[j][1]);
    }

    // epilogue: bf16-round, scale, RMW into g_lg
    size_t base = (size_t)bn * TT * SS;
    #pragma unroll
    for (int i = 0; i < 4; i++) {
        int t0 = trow0 + m_base + i * 16 + g;
        #pragma unroll
        for (int j = 0; j < 4; j++) {
            int s = srow0 + n_base + j * 8 + tg * 2;
            float q00 = __bfloat162float(__float2bfloat16(acc[i][j][0])) * 0.125f;
            float q01 = __bfloat162float(__float2bfloat16(acc[i][j][1])) * 0.125f;
            float q10 = __bfloat162float(__float2bfloat16(acc[i][j][2])) * 0.125f;
            float q11 = __bfloat162float(__float2bfloat16(acc[i][j][3])) * 0.125f;
            float2* p0 = (float2*)&g_lg[base + (size_t)t0 * SS + s];
            float2* p1 = (float2*)&g_lg[base + (size_t)(t0 + 8) * SS + s];
            float2 v0 = *p0, v1 = *p1;
            v0.x += q00; v0.y += q01;
            v1.x += q10; v1.y += q11;
            *p0 = v0; *p1 = v1;
        }
    }
}

// =====================================================================
// softmax stats: per row max + sum(exp(l - max)), single read of logits
// =====================================================================
__global__ void __launch_bounds__(256) rk_stats()
{
    const int row = blockIdx.x;
    const float* p = g_lg + (size_t)row * SS;
    __shared__ float red[256];
    const int tid = threadIdx.x;
    float r[8];
    #pragma unroll
    for (int w = 0; w < 8; w++) r[w] = p[tid + 256 * w];
    float m = r[0];
    #pragma unroll
    for (int w = 1; w < 8; w++) m = fmaxf(m, r[w]);
    red[tid] = m; __syncthreads();
    for (int off = 128; off > 0; off >>= 1) {
        if (tid < off) red[tid] = fmaxf(red[tid], red[tid + off]);
        __syncthreads();
    }
    m = red[0];
    __syncthreads();
    float s = 0.f;
    #pragma unroll
    for (int w = 0; w < 8; w++) s += expf(r[w] - m);
    red[tid] = s; __syncthreads();
    for (int off = 128; off > 0; off >>= 1) {
        if (tid < off) red[tid] += red[tid + off];
        __syncthreads();
    }
    if (tid == 0) { g_max[row] = m; g_sum[row] = red[0]; }
}

// =====================================================================
// HMMA pv: out[t,h] = bf16(probs) @ v. tile 128(t) x 64(h), K=2048 in 64-chunks.
// 8 warps: warp tile 32x32 (warp_m = wid>>1, warp_n = wid&1).
// =====================================================================
__global__ void __launch_bounds__(256) rk_pv_mma()
{
    __shared__ __nv_bfloat16 As[128][72];   // probs chunk 128 x 64
    __shared__ __nv_bfloat16 Bs[64][72];    // vT chunk   64(h) x 64(s)
    __shared__ float s_max[128], s_sum[128];
    const int tid = threadIdx.x, wid = tid >> 5, lane = tid & 31;
    const int g = lane >> 2, tg = lane & 3;
    const int bn = blockIdx.z;
    const int trow0 = blockIdx.x * 128;
    const int m_base = (wid >> 1) * 32, n_base = (wid & 1) * 32;

    if (tid < 128) {
        s_max[tid] = g_max[bn * TT + trow0 + tid];
        s_sum[tid] = g_sum[bn * TT + trow0 + tid];
    }
    __syncthreads();

    const float* Lg = g_lg + (size_t)bn * TT * SS + (size_t)trow0 * SS;
    const __nv_bfloat16* Vt = g_vbT + (size_t)bn * HH * SS;
    const int prow = tid >> 1, pc0 = (tid & 1) * 32;   // probs: 2 thr/row, 32 cols each
    const float mrow = s_max[prow], srow = s_sum[prow];
    const int vrow = tid >> 2, vc0 = (tid & 3) * 16;   // vT: 4 thr/row, 16 cols each

    float acc[2][4][4] = {};
    for (int ck = 0; ck < 32; ck++) {
        const int s0 = ck * 64;
        __syncthreads();   // previous iteration's frag reads done
        // build probs tile (exact reference rounding: expf, __fdiv_rn, bf16 rn)
        {
            const float4* lp = (const float4*)(Lg + (size_t)prow * SS + s0 + pc0);
            unsigned pw[16];
            #pragma unroll
            for (int q = 0; q < 8; q++) {
                float4 x = lp[q];
                float u0 = __fdiv_rn(expf(x.x - mrow), srow);
                float u1 = __fdiv_rn(expf(x.y - mrow), srow);
                float u2 = __fdiv_rn(expf(x.z - mrow), srow);
                float u3 = __fdiv_rn(expf(x.w - mrow), srow);
                pw[q*2]   = pack_bf2(u0, u1);
                pw[q*2+1] = pack_bf2(u2, u3);
            }
            uint4* dst = (uint4*)&As[prow][pc0];
            #pragma unroll
            for (int q = 0; q < 4; q++)
                dst[q] = make_uint4(pw[q*4], pw[q*4+1], pw[q*4+2], pw[q*4+3]);
        }
        // load vT tile
        {
            const uint4* vp = (const uint4*)(Vt + (size_t)vrow * SS + s0 + vc0);
            uint4* dst = (uint4*)&Bs[vrow][vc0];
            dst[0] = vp[0];
            dst[1] = vp[1];
        }
        __syncthreads();
        #pragma unroll
        for (int kk = 0; kk < 64; kk += 16) {
            unsigned af[2][4], bf[4][2];
            #pragma unroll
            for (int i = 0; i < 2; i++) {
                int mr = m_base + i * 16 + g;
                af[i][0] = *(const unsigned*)&As[mr    ][kk + tg*2];
                af[i][1] = *(const unsigned*)&As[mr + 8][kk + tg*2];
                af[i][2] = *(const unsigned*)&As[mr    ][kk + 8 + tg*2];
                af[i][3] = *(const unsigned*)&As[mr + 8][kk + 8 + tg*2];
            }
            #pragma unroll
            for (int j = 0; j < 4; j++) {
                int nr = n_base + j * 8 + g;
                bf[j][0] = *(const unsigned*)&Bs[nr][kk + tg*2];
                bf[j][1] = *(const unsigned*)&Bs[nr][kk + 8 + tg*2];
            }
            #pragma unroll
            for (int i = 0; i < 2; i++)
                #pragma unroll
                for (int j = 0; j < 4; j++)
                    mma16816(acc[i][j], af[i][0], af[i][1], af[i][2], af[i][3], bf[j][0], bf[j][1]);
        }
    }

    // epilogue: bf16-round into g_ob [b*t][n*h]
    const int b_ = bn >> 4, n = bn & 15;
    #pragma unroll
    for (int i = 0; i < 2; i++) {
        int t0 = trow0 + m_base + i * 16 + g;
        #pragma unroll
        for (int j = 0; j < 4; j++) {
            int h = n_base + j * 8 + tg * 2;
            *(unsigned*)&g_ob[(size_t)(b_ * TT + t0    ) * NHD + n * HH + h] =
                pack_bf2(acc[i][j][0], acc[i][j][1]);
            *(unsigned*)&g_ob[(size_t)(b_ * TT + t0 + 8) * NHD + n * HH + h] =
                pack_bf2(acc[i][j][2], acc[i][j][3]);
        }
    }
}

// =====================================================================
// final: y = fp32(out_b) @ Wout + b_out
// =====================================================================
__global__ void __launch_bounds__(256) rk_out(const float* __restrict__ Wout,
                                              const float* __restrict__ bo,
                                              float* __restrict__ out)
{
    FF_DECL();
    const int row0 = blockIdx.x * 128, col0 = blockIdx.y * 128;
    for (int kk = 0; kk < NHD; kk += 8) {
        FF_LOAD_A_BF16(g_ob + (size_t)row0 * NHD + kk, NHD);
        FF_LOAD_B_ROW(Wout + (size_t)kk * FF + col0, FF);
        __syncthreads();
        FF_COMPUTE();
        __syncthreads();
    }
    const int cbase = col0 + tx8;
    float b8[8];
    #pragma unroll
    for (int j = 0; j < 8; j++) b8[j] = bo[cbase + j];
    #pragma unroll
    for (int i = 0; i < 8; i++) {
        int r = row0 + ty8 + i;
        size_t o = (size_t)r * FF + cbase;
        *(float4*)&out[o]     = make_float4(acc[i][0]+b8[0], acc[i][1]+b8[1], acc[i][2]+b8[2], acc[i][3]+b8[3]);
        *(float4*)&out[o + 4] = make_float4(acc[i][4]+b8[4], acc[i][5]+b8[5], acc[i][6]+b8[6], acc[i][7]+b8[7]);
    }
}

extern "C" void kernel_launch(void* const* d_in, const int* in_sizes, int n_in,
                              void* d_out, int out_size)
{
    (void)in_sizes; (void)n_in; (void)out_size;
    const float* x    = (const float*)d_in[0];
    const float* rel  = (const float*)d_in[1];
    const float* mem  = (const float*)d_in[2];
    const float* Wq   = (const float*)d_in[3];
    const float* Wk   = (const float*)d_in[4];
    const float* Wv   = (const float*)d_in[5];
    const float* Wr   = (const float*)d_in[6];
    const float* ub   = (const float*)d_in[7];
    const float* vb   = (const float*)d_in[8];
    const float* Wout = (const float*)d_in[9];
    const float* bo   = (const float*)d_in[10];
    float* out = (float*)d_out;

    rk_proj_q <<<dim3(BB*TT/128, NHD/128), 256>>>(x, Wq, ub, vb);
    rk_proj_k <<<dim3(BB*SS/128, NHD/128), 256>>>(mem, Wk);
    rk_proj_v <<<dim3(BB*SS/128, NHD/128), 256>>>(mem, Wv);
    rk_proj_r <<<dim3((MM+127)/128, NHD/128), 256>>>(rel, Wr);
    rk_bd     <<<dim3(TT/128, (MM+127)/128, BB*NN_), 256>>>();
    rk_zdiag  <<<BB*NN_, TT>>>();
    rk_qk_mma <<<dim3(TT/128, SS/128, BB*NN_), 256>>>();
    rk_stats  <<<BB*NN_*TT, 256>>>();
    rk_pv_mma <<<dim3(TT/128, 1, BB*NN_), 256>>>();
    rk_out    <<<dim3(BB*TT/128, FF/128), 256>>>(Wout, bo, out);
}

// round 8
// speedup vs baseline: 1.8773x; 1.1201x over previous
#include <cuda_runtime.h>
#include <cuda_bf16.h>
#include <math.h>

#define BB   2
#define TT   1024
#define SS   2048
#define FF   1024
#define NN_  16
#define HH   64
#define MM   2049
#define NHD  1024

// ---- scratch (device globals; no allocations allowed) ----
static __device__ __nv_bfloat16 g_qu [BB*NN_*TT*HH];          // bf16(q + u_bias), [b][n][t][h]
static __device__ float         g_qv [BB*NN_*TT*HH];          // fp32 q + v_bias,  [b][n][t][h]
static __device__ __nv_bfloat16 g_kb [BB*NN_*SS*HH];          // bf16 k, [b][n][s][h]
static __device__ __nv_bfloat16 g_vb [BB*NN_*SS*HH];          // bf16 v, [b][n][s][h]
static __device__ float         g_r  [NN_*MM*HH];             // fp32 r, [n][m][h]
static __device__ float         g_lg [(size_t)BB*NN_*TT*SS];  // bias -> logits (256MB)
static __device__ float         g_max[BB*NN_*TT];             // softmax row max
static __device__ float         g_sum[BB*NN_*TT];             // softmax denominators
static __device__ __nv_bfloat16 g_ob [BB*TT*NHD];             // bf16 attention output, [b*t][n*h]

__device__ __forceinline__ unsigned pack_bf2(float a, float b) {
    __nv_bfloat162 p = __floats2bfloat162_rn(a, b);
    return *(unsigned*)&p;
}
__device__ __forceinline__ unsigned pack_u16(__nv_bfloat16 a, __nv_bfloat16 b) {
    unsigned short ua = *(unsigned short*)&a, ub2 = *(unsigned short*)&b;
    return (unsigned)ua | ((unsigned)ub2 << 16);
}

// ---- warp-level bf16 tensor-core mma (plain sm_103-safe PTX) ----
__device__ __forceinline__ void mma16816(float* d,
                                         unsigned a0, unsigned a1, unsigned a2, unsigned a3,
                                         unsigned b0, unsigned b1) {
    asm volatile(
        "mma.sync.aligned.m16n8k16.row.col.f32.bf16.bf16.f32 "
        "{%0,%1,%2,%3}, {%4,%5,%6,%7}, {%8,%9}, {%0,%1,%2,%3};"
        : "+f"(d[0]), "+f"(d[1]), "+f"(d[2]), "+f"(d[3])
        : "r"(a0), "r"(a1), "r"(a2), "r"(a3), "r"(b0), "r"(b1));
}

// =====================================================================
// FFMA GEMM skeleton: 64(M) x 128(N) tile, 256 threads, 8x4 per thread,
// K-step 8. Exact fp32 numerics (sequential-K fmaf accumulation).
// =====================================================================
#define F64_DECL() \
    __shared__ float As[8][72];   /* [k][m], 64 m + pad */ \
    __shared__ float Bs[8][132];  /* [k][n], 128 n + pad */ \
    const int tid = threadIdx.x; \
    const int ty = tid >> 5, tx = tid & 31; \
    float acc[8][4] = {};

// A fp32 row-major [M][K]; AP already = base + row0*LDA; guarded by LIM rows
#define F64_LOAD_A(AP, LDA, KK, LIM) { \
    int r_ = tid >> 2, kc_ = (tid & 3) << 1; \
    float2 v_ = make_float2(0.f, 0.f); \
    if (r_ < (LIM)) v_ = *(const float2*)((AP) + (size_t)r_ * (LDA) + (KK) + kc_); \
    As[kc_][r_] = v_.x; As[kc_ + 1][r_] = v_.y; }

// B fp32 row-major [K][N]; BP already = base + col0
#define F64_LOAD_B_ROW(BP, LDB, KK) { \
    int kr_ = tid >> 5, c_ = (tid & 31) << 2; \
    float4 v_ = *(const float4*)((BP) + (size_t)((KK) + kr_) * (LDB) + c_); \
    *(float4*)&Bs[kr_][c_] = v_; }

// B from [N][K] source (transposed); BP = base + col0*LDB; guarded
#define F64_LOAD_B_TRANS(BP, LDB, KK, LIM) { \
    int n_ = tid >> 1, kc_ = (tid & 1) << 2; \
    float4 v_ = make_float4(0.f, 0.f, 0.f, 0.f); \
    if (n_ < (LIM)) v_ = *(const float4*)((BP) + (size_t)n_ * (LDB) + (KK) + kc_); \
    Bs[kc_ + 0][n_] = v_.x; Bs[kc_ + 1][n_] = v_.y; \
    Bs[kc_ + 2][n_] = v_.z; Bs[kc_ + 3][n_] = v_.w; }

#define F64_COMPUTE() { \
    _Pragma("unroll") \
    for (int k_ = 0; k_ < 8; k_++) { \
        float4 a0 = *(const float4*)&As[k_][ty * 8]; \
        float4 a1 = *(const float4*)&As[k_][ty * 8 + 4]; \
        float4 b  = *(const float4*)&Bs[k_][tx * 4]; \
        float av[8] = {a0.x, a0.y, a0.z, a0.w, a1.x, a1.y, a1.z, a1.w}; \
        float bv[4] = {b.x, b.y, b.z, b.w}; \
        _Pragma("unroll") for (int i_ = 0; i_ < 8; i_++) \
        _Pragma("unroll") for (int j_ = 0; j_ < 4; j_++) \
            acc[i_][j_] = fmaf(av[i_], bv[j_], acc[i_][j_]); \
    } }

// =====================================================================
// Projection q: x @ Wq -> qu bf16(+ub), qv fp32(+vb), BNTH
// =====================================================================
__global__ void __launch_bounds__(256) rk_proj_q(const float* __restrict__ A,
                                                 const float* __restrict__ W,
                                                 const float* __restrict__ ub,
                                                 const float* __restrict__ vb)
{
    F64_DECL();
    const int row0 = blockIdx.x * 64, col0 = blockIdx.y * 128;
    const float* AP = A + (size_t)row0 * FF;
    for (int kk = 0; kk < FF; kk += 8) {
        F64_LOAD_A(AP, FF, kk, 1 << 30);
        F64_LOAD_B_ROW(W + col0, NHD, kk);
        __syncthreads();
        F64_COMPUTE();
        __syncthreads();
    }
    const int c0 = col0 + tx * 4;
    const int n = c0 >> 6, h = c0 & 63;
    float u0 = ub[c0], u1 = ub[c0+1], u2 = ub[c0+2], u3 = ub[c0+3];
    float v0 = vb[c0], v1 = vb[c0+1], v2 = vb[c0+2], v3 = vb[c0+3];
    #pragma unroll
    for (int i = 0; i < 8; i++) {
        int r = row0 + ty * 8 + i;
        int b_ = r >> 10, t = r & 1023;
        size_t o = ((size_t)(b_ * NN_ + n) * TT + t) * HH + h;
        *(uint2*)&g_qu[o] = make_uint2(pack_bf2(acc[i][0] + u0, acc[i][1] + u1),
                                       pack_bf2(acc[i][2] + u2, acc[i][3] + u3));
        *(float4*)&g_qv[o] = make_float4(acc[i][0] + v0, acc[i][1] + v1,
                                         acc[i][2] + v2, acc[i][3] + v3);
    }
}

// =====================================================================
// Projection k / v (dst selects), BNSH bf16
// =====================================================================
__global__ void __launch_bounds__(256) rk_proj_kv(const float* __restrict__ A,
                                                  const float* __restrict__ W,
                                                  int which)
{
    F64_DECL();
    const int row0 = blockIdx.x * 64, col0 = blockIdx.y * 128;
    const float* AP = A + (size_t)row0 * FF;
    for (int kk = 0; kk < FF; kk += 8) {
        F64_LOAD_A(AP, FF, kk, 1 << 30);
        F64_LOAD_B_ROW(W + col0, NHD, kk);
        __syncthreads();
        F64_COMPUTE();
        __syncthreads();
    }
    __nv_bfloat16* dst = which ? g_vb : g_kb;
    const int c0 = col0 + tx * 4;
    const int n = c0 >> 6, h = c0 & 63;
    #pragma unroll
    for (int i = 0; i < 8; i++) {
        int r = row0 + ty * 8 + i;
        int b_ = r >> 11, s = r & 2047;
        size_t o = ((size_t)(b_ * NN_ + n) * SS + s) * HH + h;
        *(uint2*)&dst[o] = make_uint2(pack_bf2(acc[i][0], acc[i][1]),
                                      pack_bf2(acc[i][2], acc[i][3]));
    }
}

// =====================================================================
// Projection r (M=2049 guard), fp32 [n][m][h]
// =====================================================================
__global__ void __launch_bounds__(256) rk_proj_r(const float* __restrict__ A,
                                                 const float* __restrict__ W)
{
    F64_DECL();
    const int row0 = blockIdx.x * 64, col0 = blockIdx.y * 128;
    const int lim = MM - row0;
    const float* AP = A + (size_t)row0 * FF;
    for (int kk = 0; kk < FF; kk += 8) {
        F64_LOAD_A(AP, FF, kk, lim);
        F64_LOAD_B_ROW(W + col0, NHD, kk);
        __syncthreads();
        F64_COMPUTE();
        __syncthreads();
    }
    const int c0 = col0 + tx * 4;
    const int n = c0 >> 6, h = c0 & 63;
    #pragma unroll
    for (int i = 0; i < 8; i++) {
        int m = row0 + ty * 8 + i;
        if (m >= MM) continue;
        size_t o = ((size_t)n * MM + m) * HH + h;
        *(float4*)&g_r[o] = make_float4(acc[i][0], acc[i][1], acc[i][2], acc[i][3]);
    }
}

// =====================================================================
// final: y = fp32(out_b) @ Wout + b_out   (A is bf16 -> upconvert in load)
// =====================================================================
__global__ void __launch_bounds__(256) rk_out(const float* __restrict__ Wout,
                                              const float* __restrict__ bo,
                                              float* __restrict__ out)
{
    F64_DECL();
    const int row0 = blockIdx.x * 64, col0 = blockIdx.y * 128;
    const __nv_bfloat16* AP = g_ob + (size_t)row0 * NHD;
    for (int kk = 0; kk < NHD; kk += 8) {
        {
            int r_ = tid >> 2, kc_ = (tid & 3) << 1;
            unsigned w = *(const unsigned*)(AP + (size_t)r_ * NHD + kk + kc_);
            __nv_bfloat162 p = *(__nv_bfloat162*)&w;
            As[kc_][r_] = __low2float(p);
            As[kc_ + 1][r_] = __high2float(p);
        }
        F64_LOAD_B_ROW(Wout + col0, FF, kk);
        __syncthreads();
        F64_COMPUTE();
        __syncthreads();
    }
    const int c0 = col0 + tx * 4;
    float b0 = bo[c0], b1 = bo[c0+1], b2 = bo[c0+2], b3 = bo[c0+3];
    #pragma unroll
    for (int i = 0; i < 8; i++) {
        int r = row0 + ty * 8 + i;
        *(float4*)&out[(size_t)r * FF + c0] =
            make_float4(acc[i][0] + b0, acc[i][1] + b1, acc[i][2] + b2, acc[i][3] + b3);
    }
}

// =====================================================================
// bd = q_v @ r^T per (b,n), scaled, scattered through the relative shift
// =====================================================================
__global__ void __launch_bounds__(256) rk_bd()
{
    F64_DECL();
    const int bn = blockIdx.z;
    const int row0 = blockIdx.x * 64, col0 = blockIdx.y * 128;
    const float* AP = g_qv + (size_t)bn * TT * HH + (size_t)row0 * HH;
    const float* BT = g_r  + (size_t)(bn & 15) * MM * HH + (size_t)col0 * HH;
    const int lim = MM - col0;
    #pragma unroll
    for (int kk = 0; kk < HH; kk += 8) {
        F64_LOAD_A(AP, HH, kk, 1 << 30);
        F64_LOAD_B_TRANS(BT, HH, kk, lim);
        __syncthreads();
        F64_COMPUTE();
        __syncthreads();
    }
    size_t base = (size_t)bn * TT * SS;
    #pragma unroll
    for (int i = 0; i < 8; i++) {
        int t = row0 + ty * 8 + i;
        #pragma unroll
        for (int j = 0; j < 4; j++) {
            int m = col0 + tx * 4 + j;
            if (m < MM) {
                float val = acc[i][j] * 0.125f;
                int s1 = m + t - 1023;
                if (s1 >= 0 && s1 < SS)
                    g_lg[base + (size_t)t * SS + s1] = val;
                if (t >= 1) {
                    int s2 = m + t + 1026;
                    if (s2 < SS)
                        g_lg[base + (size_t)(t - 1) * SS + s2] = val;
                }
            }
        }
    }
}

// zero the d == 1026 diagonal (never written by the scatter)
__global__ void rk_zdiag()
{
    int bn = blockIdx.x;
    int t  = threadIdx.x;
    int s  = t + 1026;
    if (s < SS)
        g_lg[(size_t)bn*TT*SS + (size_t)t*SS + s] = 0.f;
}

// =====================================================================
// HMMA qk: logits[t,s] = bf16round(qk)*scale + bias  (RMW g_lg)
// tile 128(t) x 128(s), K=64. 8 warps: warp tile 64x32.  (R4-proven)
// =====================================================================
__global__ void __launch_bounds__(256) rk_qk_mma()
{
    __shared__ __nv_bfloat16 As[128][72];
    __shared__ __nv_bfloat16 Bs[128][72];
    const int tid = threadIdx.x, wid = tid >> 5, lane = tid & 31;
    const int g = lane >> 2, tg = lane & 3;
    const int bn = blockIdx.z;
    const int trow0 = blockIdx.x * 128, srow0 = blockIdx.y * 128;
    const int m_base = (wid >> 2) * 64, n_base = (wid & 3) * 32;

    {
        const __nv_bfloat16* Ag = g_qu + ((size_t)bn * TT + trow0) * HH;
        const __nv_bfloat16* Bg = g_kb + ((size_t)bn * SS + srow0) * HH;
        int r = tid >> 1, c0 = (tid & 1) * 32;
        const uint4* as = (const uint4*)(Ag + (size_t)r * HH + c0);
        const uint4* bs = (const uint4*)(Bg + (size_t)r * HH + c0);
        uint4* ad = (uint4*)&As[r][c0];
        uint4* bd = (uint4*)&Bs[r][c0];
        #pragma unroll
        for (int q = 0; q < 4; q++) { ad[q] = as[q]; bd[q] = bs[q]; }
    }
    __syncthreads();

    float acc[4][4][4] = {};
    #pragma unroll
    for (int kk = 0; kk < 64; kk += 16) {
        unsigned af[4][4], bf[4][2];
        #pragma unroll
        for (int i = 0; i < 4; i++) {
            int mr = m_base + i * 16 + g;
            af[i][0] = *(const unsigned*)&As[mr    ][kk + tg*2];
            af[i][1] = *(const unsigned*)&As[mr + 8][kk + tg*2];
            af[i][2] = *(const unsigned*)&As[mr    ][kk + 8 + tg*2];
            af[i][3] = *(const unsigned*)&As[mr + 8][kk + 8 + tg*2];
        }
        #pragma unroll
        for (int j = 0; j < 4; j++) {
            int nr = n_base + j * 8 + g;
            bf[j][0] = *(const unsigned*)&Bs[nr][kk + tg*2];
            bf[j][1] = *(const unsigned*)&Bs[nr][kk + 8 + tg*2];
        }
        #pragma unroll
        for (int i = 0; i < 4; i++)
            #pragma unroll
            for (int j = 0; j < 4; j++)
                mma16816(acc[i][j], af[i][0], af[i][1], af[i][2], af[i][3], bf[j][0], bf[j][1]);
    }

    size_t base = (size_t)bn * TT * SS;
    #pragma unroll
    for (int i = 0; i < 4; i++) {
        int t0 = trow0 + m_base + i * 16 + g;
        #pragma unroll
        for (int j = 0; j < 4; j++) {
            int s = srow0 + n_base + j * 8 + tg * 2;
            float q00 = __bfloat162float(__float2bfloat16(acc[i][j][0])) * 0.125f;
            float q01 = __bfloat162float(__float2bfloat16(acc[i][j][1])) * 0.125f;
            float q10 = __bfloat162float(__float2bfloat16(acc[i][j][2])) * 0.125f;
            float q11 = __bfloat162float(__float2bfloat16(acc[i][j][3])) * 0.125f;
            float2* p0 = (float2*)&g_lg[base + (size_t)t0 * SS + s];
            float2* p1 = (float2*)&g_lg[base + (size_t)(t0 + 8) * SS + s];
            float2 v0 = *p0, v1 = *p1;
            v0.x += q00; v0.y += q01;
            v1.x += q10; v1.y += q11;
            *p0 = v0; *p1 = v1;
        }
    }
}

// =====================================================================
// softmax stats: per row max + sum(exp(l - max)), single read of logits
// =====================================================================
__global__ void __launch_bounds__(256) rk_stats()
{
    const int row = blockIdx.x;
    const float* p = g_lg + (size_t)row * SS;
    __shared__ float red[256];
    const int tid = threadIdx.x;
    float r[8];
    #pragma unroll
    for (int w = 0; w < 8; w++) r[w] = p[tid + 256 * w];
    float m = r[0];
    #pragma unroll
    for (int w = 1; w < 8; w++) m = fmaxf(m, r[w]);
    red[tid] = m; __syncthreads();
    for (int off = 128; off > 0; off >>= 1) {
        if (tid < off) red[tid] = fmaxf(red[tid], red[tid + off]);
        __syncthreads();
    }
    m = red[0];
    __syncthreads();
    float s = 0.f;
    #pragma unroll
    for (int w = 0; w < 8; w++) s += expf(r[w] - m);
    red[tid] = s; __syncthreads();
    for (int off = 128; off > 0; off >>= 1) {
        if (tid < off) red[tid] += red[tid + off];
        __syncthreads();
    }
    if (tid == 0) { g_max[row] = m; g_sum[row] = red[0]; }
}

// =====================================================================
// HMMA pv: out[t,h] = bf16(probs) @ v. tile 128(t) x 64(h), K=2048 in 64-chunks.
// B fragments gathered k-major from g_vb [s][h].  (bf16-exact, R5-proven path)
// =====================================================================
__global__ void __launch_bounds__(256) rk_pv_mma()
{
    __shared__ __nv_bfloat16 As[128][72];   // probs chunk 128(t) x 64(s)
    __shared__ __nv_bfloat16 Bs[64][72];    // v chunk 64(s) x 64(h)
    __shared__ float s_max[128], s_sum[128];
    const int tid = threadIdx.x, wid = tid >> 5, lane = tid & 31;
    const int g = lane >> 2, tg = lane & 3;
    const int bn = blockIdx.z;
    const int trow0 = blockIdx.x * 128;
    const int m_base = (wid >> 1) * 32, n_base = (wid & 1) * 32;

    if (tid < 128) {
        s_max[tid] = g_max[bn * TT + trow0 + tid];
        s_sum[tid] = g_sum[bn * TT + trow0 + tid];
    }
    __syncthreads();

    const float* Lg = g_lg + (size_t)bn * TT * SS + (size_t)trow0 * SS;
    const __nv_bfloat16* Vg = g_vb + (size_t)bn * SS * HH;
    const int prow = tid >> 1, pc0 = (tid & 1) * 32;
    const float mrow = s_max[prow], srow = s_sum[prow];
    const int vrow = tid >> 2, vc0 = (tid & 3) * 16;

    float acc[2][4][4] = {};
    for (int ck = 0; ck < 32; ck++) {
        const int s0 = ck * 64;
        __syncthreads();
        {
            const float4* lp = (const float4*)(Lg + (size_t)prow * SS + s0 + pc0);
            unsigned pw[16];
            #pragma unroll
            for (int q = 0; q < 8; q++) {
                float4 x = lp[q];
                float u0 = __fdiv_rn(expf(x.x - mrow), srow);
                float u1 = __fdiv_rn(expf(x.y - mrow), srow);
                float u2 = __fdiv_rn(expf(x.z - mrow), srow);
                float u3 = __fdiv_rn(expf(x.w - mrow), srow);
                pw[q*2]   = pack_bf2(u0, u1);
                pw[q*2+1] = pack_bf2(u2, u3);
            }
            uint4* dst = (uint4*)&As[prow][pc0];
            #pragma unroll
            for (int q = 0; q < 4; q++)
                dst[q] = make_uint4(pw[q*4], pw[q*4+1], pw[q*4+2], pw[q*4+3]);
        }
        {
            const uint4* vp = (const uint4*)(Vg + (size_t)(s0 + vrow) * HH + vc0);
            uint4* dst = (uint4*)&Bs[vrow][vc0];
            dst[0] = vp[0];
            dst[1] = vp[1];
        }
        __syncthreads();
        #pragma unroll
        for (int kk = 0; kk < 64; kk += 16) {
            unsigned af[2][4], bf[4][2];
            #pragma unroll
            for (int i = 0; i < 2; i++) {
                int mr = m_base + i * 16 + g;
                af[i][0] = *(const unsigned*)&As[mr    ][kk + tg*2];
                af[i][1] = *(const unsigned*)&As[mr + 8][kk + tg*2];
                af[i][2] = *(const unsigned*)&As[mr    ][kk + 8 + tg*2];
                af[i][3] = *(const unsigned*)&As[mr + 8][kk + 8 + tg*2];
            }
            #pragma unroll
            for (int j = 0; j < 4; j++) {
                int nr = n_base + j * 8 + g;
                bf[j][0] = pack_u16(Bs[kk + tg*2][nr],     Bs[kk + tg*2 + 1][nr]);
                bf[j][1] = pack_u16(Bs[kk + 8 + tg*2][nr], Bs[kk + 8 + tg*2 + 1][nr]);
            }
            #pragma unroll
            for (int i = 0; i < 2; i++)
                #pragma unroll
                for (int j = 0; j < 4; j++)
                    mma16816(acc[i][j], af[i][0], af[i][1], af[i][2], af[i][3], bf[j][0], bf[j][1]);
        }
    }

    const int b_ = bn >> 4, n = bn & 15;
    #pragma unroll
    for (int i = 0; i < 2; i++) {
        int t0 = trow0 + m_base + i * 16 + g;
        #pragma unroll
        for (int j = 0; j < 4; j++) {
            int h = n_base + j * 8 + tg * 2;
            *(unsigned*)&g_ob[(size_t)(b_ * TT + t0    ) * NHD + n * HH + h] =
                pack_bf2(acc[i][j][0], acc[i][j][1]);
            *(unsigned*)&g_ob[(size_t)(b_ * TT + t0 + 8) * NHD + n * HH + h] =
                pack_bf2(acc[i][j][2], acc[i][j][3]);
        }
    }
}

extern "C" void kernel_launch(void* const* d_in, const int* in_sizes, int n_in,
                              void* d_out, int out_size)
{
    (void)in_sizes; (void)n_in; (void)out_size;
    const float* x    = (const float*)d_in[0];
    const float* rel  = (const float*)d_in[1];
    const float* mem  = (const float*)d_in[2];
    const float* Wq   = (const float*)d_in[3];
    const float* Wk   = (const float*)d_in[4];
    const float* Wv   = (const float*)d_in[5];
    const float* Wr   = (const float*)d_in[6];
    const float* ub   = (const float*)d_in[7];
    const float* vb   = (const float*)d_in[8];
    const float* Wout = (const float*)d_in[9];
    const float* bo   = (const float*)d_in[10];
    float* out = (float*)d_out;

    rk_proj_q <<<dim3(BB*TT/64, NHD/128), 256>>>(x, Wq, ub, vb);
    rk_proj_kv<<<dim3(BB*SS/64, NHD/128), 256>>>(mem, Wk, 0);
    rk_proj_kv<<<dim3(BB*SS/64, NHD/128), 256>>>(mem, Wv, 1);
    rk_proj_r <<<dim3((MM+63)/64, NHD/128), 256>>>(rel, Wr);
    rk_bd     <<<dim3(TT/64, (MM+127)/128, BB*NN_), 256>>>();
    rk_zdiag  <<<BB*NN_, TT>>>();
    rk_qk_mma <<<dim3(TT/128, SS/128, BB*NN_), 256>>>();
    rk_stats  <<<BB*NN_*TT, 256>>>();
    rk_pv_mma <<<dim3(TT/128, 1, BB*NN_), 256>>>();
    rk_out    <<<dim3(BB*TT/64, FF/128), 256>>>(Wout, bo, out);
}